// round 10
// baseline (speedup 1.0000x reference)
#include <cuda_runtime.h>
#include <math.h>

#define NN 2048
#define MM 2048
#define KC 8
#define DD 64

#define FAB_OFF 0
#define GAB_OFF NN
#define FAA_OFF (NN + MM)
#define GBB_OFF (2 * NN + MM)
#define POT_SZ  (2 * (NN + MM))
#define NROWS   (2 * (NN + MM))
#define NSEG    (4 * KC)

#define LOG2E_F 1.4426950408889634f
#define LN2_F   0.6931471805599453f
#define SENT    -3.4e38f

#define GRIDB 148
#define COST_GRID 4416

// -------------------- static device scratch ---------------------------------
__device__ int   g_predx[NN];
__device__ int   g_ix[NN], g_iy[MM];
__device__ int   g_clx[NN], g_cly[MM];
__device__ int   g_cntx[KC], g_cnty[KC];
__device__ int   g_offx[KC + 1], g_offy[KC + 1];
__device__ int   g_offXY[KC + 1], g_offYX[KC + 1], g_offXX[KC + 1], g_offYY[KC + 1]; // PADDED offsets
__device__ float g_l2cx[KC], g_l2cy[KC];
__device__ int   g_valid[KC];
__device__ float g_lossfil;
__device__ int   g_tOff[NSEG + 1];
__device__ unsigned g_barCnt;
__device__ unsigned g_exitCnt;
__device__ float g_hx[NN], g_hy[MM];
// 32 row-segments (4 per cluster): closed-form row descriptors
__device__ int    g_segRow[NSEG + 1];   // first row of segment
__device__ int    g_segCol[NSEG + 1];   // column prefix at segment start
__device__ int    g_segN[NSEG];         // logical row length
__device__ int    g_segStride[NSEG];    // padded stride (multiple of 4)
__device__ int    g_segPot[NSEG];       // pot input segment offset
__device__ int    g_segOut[NSEG];       // output base index
__device__ float  g_segB2[NSEG];
__device__ float* g_segC[NSEG];         // C base pointer
// cost matrices (padded rows; +4*rows margin)
__device__ float g_Cxy[(size_t)NN * MM + 4 * NN];
__device__ float g_Cyx[(size_t)NN * MM + 4 * MM];
__device__ float g_Cxx[(size_t)NN * NN + 4 * NN];
__device__ float g_Cyy[(size_t)MM * MM + 4 * MM];
__device__ float g_pot[2][POT_SZ];

__device__ __forceinline__ float ex2_fast(float x) {
    float r;
    asm("ex2.approx.ftz.f32 %0, %1;" : "=f"(r) : "f"(x));
    return r;
}
__device__ __forceinline__ void red_release_add1(unsigned* p) {
    asm volatile("red.release.gpu.add.u32 [%0], 1;" :: "l"(p) : "memory");
}
__device__ __forceinline__ unsigned ld_acquire_u32(unsigned* p) {
    unsigned v;
    asm volatile("ld.acquire.gpu.u32 %0, [%1];" : "=r"(v) : "l"(p) : "memory");
    return v;
}

// -------------------- 1) fused assign + norms -------------------------------
__global__ void k_prep(const float* __restrict__ x, const float* __restrict__ cc,
                       const float* __restrict__ y) {
    __shared__ float scc[KC * DD];
    for (int idx = threadIdx.x; idx < KC * DD; idx += blockDim.x) scc[idx] = cc[idx];
    __syncthreads();
    int t = blockIdx.x * blockDim.x + threadIdx.x;
    if (t < NN) {
        float xr[DD];
        float nrm = 0.f;
        const float4* xv = reinterpret_cast<const float4*>(x + (size_t)t * DD);
#pragma unroll
        for (int q = 0; q < DD / 4; q++) {
            float4 v = xv[q];
            xr[q*4+0]=v.x; xr[q*4+1]=v.y; xr[q*4+2]=v.z; xr[q*4+3]=v.w;
            nrm += v.x*v.x + v.y*v.y + v.z*v.z + v.w*v.w;
        }
        g_hx[t] = 0.5f * nrm;
        float best = 3.4e38f; int bk = 0;
#pragma unroll
        for (int k = 0; k < KC; k++) {
            float s = 0.f;
#pragma unroll 16
            for (int d = 0; d < DD; d++) {
                float u = xr[d] - scc[k * DD + d];
                s = fmaf(u, u, s);
            }
            if (s < best) { best = s; bk = k; }
        }
        g_predx[t] = bk;
    } else if (t < NN + MM) {
        int j = t - NN;
        const float4* v = reinterpret_cast<const float4*>(y + (size_t)j * DD);
        float s = 0.f;
#pragma unroll
        for (int q = 0; q < DD / 4; q++) { float4 a = v[q]; s += a.x*a.x + a.y*a.y + a.z*a.z + a.w*a.w; }
        g_hy[j] = 0.5f * s;
    }
}

// -------------------- 2) lists + offsets + segment tables -------------------
__global__ void k_lists(const int* __restrict__ predy32, const float* __restrict__ fill) {
    __shared__ int sBase[2][KC];
    __shared__ int sCnt[2][KC];
    __shared__ int sOr;
    int w = threadIdx.x >> 5, lane = threadIdx.x & 31;

    if (threadIdx.x == 0) sOr = 0;
    __syncthreads();
    int orv = 0;
    for (int i = threadIdx.x; i < MM / 2; i += blockDim.x) orv |= predy32[2 * i + 1];
    atomicOr(&sOr, orv);
    __syncthreads();
    const int stride = (sOr == 0) ? 2 : 1;   // int64 (odd words 0) vs int32

    if (w < 2) {
        int nElem = (w == 0) ? NN : MM;
        int cnt[KC];
#pragma unroll
        for (int k = 0; k < KC; k++) cnt[k] = 0;
        for (int ch = 0; ch < nElem / 32; ch++) {
            int i = ch * 32 + lane;
            int v = (w == 0) ? g_predx[i] : (predy32[i * stride] & 7);
#pragma unroll
            for (int k = 0; k < KC; k++) cnt[k] += (v == k);
        }
#pragma unroll
        for (int k = 0; k < KC; k++) {
            int s = cnt[k];
            for (int o = 16; o; o >>= 1) s += __shfl_down_sync(0xffffffffu, s, o);
            if (lane == 0) sCnt[w][k] = s;
        }
        __syncwarp();
        if (lane == 0) {
            int off = 0;
            for (int k = 0; k < KC; k++) {
                int c = sCnt[w][k];
                sBase[w][k] = off;
                if (w == 0) { g_cntx[k] = c; g_offx[k] = off; }
                else        { g_cnty[k] = c; g_offy[k] = off; }
                off += c;
            }
            if (w == 0) g_offx[KC] = off; else g_offy[KC] = off;
        }
        __syncwarp();
        for (int ch = 0; ch < nElem / 32; ch++) {
            int i = ch * 32 + lane;
            int v = (w == 0) ? g_predx[i] : (predy32[i * stride] & 7);
            unsigned mask = __match_any_sync(0xffffffffu, v);
            unsigned lt = (1u << lane) - 1u;
            int rank = __popc(mask & lt);
            int myBase = sBase[w][v];
            __syncwarp();
            int pos = myBase + rank;
            if (w == 0) { g_ix[pos] = i; g_clx[pos] = v; }
            else        { g_iy[pos] = i; g_cly[pos] = v; }
            if ((mask & lt) == 0) sBase[w][v] = myBase + __popc(mask);
            __syncwarp();
        }
    }
    __syncthreads();
    if (threadIdx.x == 0) {
        float lf = 0.f;
        int oXY = 0, oYX = 0, oXX = 0, oYY = 0;
        int rowAcc = 0, colAcc = 0;
        for (int k = 0; k < KC; k++) {
            int cx = g_cntx[k], cy = g_cnty[k];
            int cxp = (cx + 3) & ~3, cyp = (cy + 3) & ~3;
            float d = (float)cx / (float)NN - fill[k];
            lf += d * d;
            float l2x = log2f((float)(cx > 0 ? cx : 1));
            float l2y = log2f((float)(cy > 0 ? cy : 1));
            g_l2cx[k] = l2x; g_l2cy[k] = l2y;
            g_valid[k] = (cx > 0 && cy > 0) ? 1 : 0;
            g_offXY[k] = oXY; g_offYX[k] = oYX; g_offXX[k] = oXX; g_offYY[k] = oYY;
            // segment tables: fab, gab, faa, gbb
            int s = 4 * k;
            g_segRow[s] = rowAcc; g_segCol[s] = colAcc;
            g_segN[s] = cy; g_segStride[s] = cyp; g_segC[s] = g_Cxy + oXY;
            g_segPot[s] = GAB_OFF + g_offy[k]; g_segOut[s] = FAB_OFF + g_offx[k];
            g_segB2[s] = -l2y;
            rowAcc += cx; colAcc += cx * cy; s++;
            g_segRow[s] = rowAcc; g_segCol[s] = colAcc;
            g_segN[s] = cx; g_segStride[s] = cxp; g_segC[s] = g_Cyx + oYX;
            g_segPot[s] = FAB_OFF + g_offx[k]; g_segOut[s] = GAB_OFF + g_offy[k];
            g_segB2[s] = -l2x;
            rowAcc += cy; colAcc += cy * cx; s++;
            g_segRow[s] = rowAcc; g_segCol[s] = colAcc;
            g_segN[s] = cx; g_segStride[s] = cxp; g_segC[s] = g_Cxx + oXX;
            g_segPot[s] = FAA_OFF + g_offx[k]; g_segOut[s] = FAA_OFF + g_offx[k];
            g_segB2[s] = -l2x;
            rowAcc += cx; colAcc += cx * cx; s++;
            g_segRow[s] = rowAcc; g_segCol[s] = colAcc;
            g_segN[s] = cy; g_segStride[s] = cyp; g_segC[s] = g_Cyy + oYY;
            g_segPot[s] = GBB_OFF + g_offy[k]; g_segOut[s] = GBB_OFF + g_offy[k];
            g_segB2[s] = -l2y;
            rowAcc += cy; colAcc += cy * cy;
            oXY += cx * cyp; oYX += cy * cxp; oXX += cx * cxp; oYY += cy * cyp;
        }
        g_segRow[NSEG] = rowAcc; g_segCol[NSEG] = colAcc;
        g_offXY[KC] = oXY; g_offYX[KC] = oYX; g_offXX[KC] = oXX; g_offYY[KC] = oYY;
        g_lossfil = lf / (float)KC;
        g_tOff[0] = 0;
        for (int f = 0; f < 4; f++)
            for (int k = 0; k < KC; k++) {
                int cx = g_cntx[k], cy = g_cnty[k];
                int nr = (f == 0 || f == 2) ? cx : cy;
                int nc = (f == 1 || f == 2) ? cx : cy;
                int idx = f * KC + k;
                g_tOff[idx + 1] = g_tOff[idx] + ((nr + 63) / 64) * ((nc + 63) / 64);
            }
    }
    __syncthreads();
    for (int i = threadIdx.x; i < POT_SZ; i += blockDim.x) g_pot[0][i] = 0.f;
}

// -------------------- 3) compact cost submatrices (padded stride) -----------
__global__ __launch_bounds__(256) void k_cost(const float* __restrict__ x,
                                              const float* __restrict__ y) {
    __shared__ float sR[64][65];
    __shared__ float sCt[64][68];
    __shared__ float sHr[64], sHc[64];
    __shared__ int sOff[NSEG + 1];
    int tid = threadIdx.x;
    if (tid < NSEG + 1) sOff[tid] = g_tOff[tid];
    __syncthreads();
    int bt = blockIdx.x;
    if (bt >= sOff[NSEG]) return;
    int e = 0;
    while (bt >= sOff[e + 1]) e++;
    int f = e >> 3, k = e & 7;
    int ti = bt - sOff[e];
    int cx = g_cntx[k], cy = g_cnty[k], ox = g_offx[k], oy = g_offy[k];
    int nr, nc, obase;
    const int *rl, *cl; const float *rp, *cp, *rh, *chv; float* outp;
    if (f == 0)      { nr = cx; nc = cy; rl = g_ix + ox; cl = g_iy + oy; rp = x; cp = y; rh = g_hx; chv = g_hy; outp = g_Cxy; obase = g_offXY[k]; }
    else if (f == 1) { nr = cy; nc = cx; rl = g_iy + oy; cl = g_ix + ox; rp = y; cp = x; rh = g_hy; chv = g_hx; outp = g_Cyx; obase = g_offYX[k]; }
    else if (f == 2) { nr = cx; nc = cx; rl = g_ix + ox; cl = g_ix + ox; rp = x; cp = x; rh = g_hx; chv = g_hx; outp = g_Cxx; obase = g_offXX[k]; }
    else             { nr = cy; nc = cy; rl = g_iy + oy; cl = g_iy + oy; rp = y; cp = y; rh = g_hy; chv = g_hy; outp = g_Cyy; obase = g_offYY[k]; }
    int ncp = (nc + 3) & ~3;            // padded stride
    int nct = (nc + 63) >> 6;
    int r0 = (ti / nct) * 64;
    int c0 = (ti % nct) * 64;
    const float F_INF = __int_as_float(0x7f800000);

    for (int idx = tid; idx < 64 * DD; idx += 256) {
        int r = idx >> 6, d = idx & 63;
        int gi = rl[min(r0 + r, nr - 1)];
        sR[r][d] = rp[(size_t)gi * DD + d];
    }
    for (int idx = tid; idx < 64 * DD; idx += 256) {
        int c = idx >> 6, d = idx & 63;
        int gi = cl[min(c0 + c, nc - 1)];
        sCt[d][c] = cp[(size_t)gi * DD + d];
    }
    if (tid < 64)       sHr[tid]      = rh[rl[min(r0 + tid, nr - 1)]];
    else if (tid < 128) sHc[tid - 64] = chv[cl[min(c0 + tid - 64, nc - 1)]];
    __syncthreads();

    int rg = tid >> 4, cg = tid & 15;
    float acc[4][4];
#pragma unroll
    for (int i = 0; i < 4; i++)
#pragma unroll
        for (int j = 0; j < 4; j++) acc[i][j] = 0.f;

#pragma unroll 8
    for (int d = 0; d < DD; d++) {
        float4 cv = *reinterpret_cast<const float4*>(&sCt[d][cg * 4]);
        float r0v = sR[rg * 4 + 0][d];
        float r1v = sR[rg * 4 + 1][d];
        float r2v = sR[rg * 4 + 2][d];
        float r3v = sR[rg * 4 + 3][d];
        acc[0][0]=fmaf(r0v,cv.x,acc[0][0]); acc[0][1]=fmaf(r0v,cv.y,acc[0][1]);
        acc[0][2]=fmaf(r0v,cv.z,acc[0][2]); acc[0][3]=fmaf(r0v,cv.w,acc[0][3]);
        acc[1][0]=fmaf(r1v,cv.x,acc[1][0]); acc[1][1]=fmaf(r1v,cv.y,acc[1][1]);
        acc[1][2]=fmaf(r1v,cv.z,acc[1][2]); acc[1][3]=fmaf(r1v,cv.w,acc[1][3]);
        acc[2][0]=fmaf(r2v,cv.x,acc[2][0]); acc[2][1]=fmaf(r2v,cv.y,acc[2][1]);
        acc[2][2]=fmaf(r2v,cv.z,acc[2][2]); acc[2][3]=fmaf(r2v,cv.w,acc[2][3]);
        acc[3][0]=fmaf(r3v,cv.x,acc[3][0]); acc[3][1]=fmaf(r3v,cv.y,acc[3][1]);
        acc[3][2]=fmaf(r3v,cv.z,acc[3][2]); acc[3][3]=fmaf(r3v,cv.w,acc[3][3]);
    }

#pragma unroll
    for (int i = 0; i < 4; i++) {
        int rr = r0 + rg * 4 + i;
        if (rr < nr) {
            float hr = sHr[rg * 4 + i];
            size_t rowb = (size_t)obase + (size_t)rr * ncp;
#pragma unroll
            for (int j = 0; j < 4; j++) {
                int cc = c0 + cg * 4 + j;
                if (cc < nc)       outp[rowb + cc] = fmaxf(hr + sHc[cg * 4 + j] - acc[i][j], 0.f);
                else if (cc < ncp) outp[rowb + cc] = F_INF;   // padding -> exp contributes 0
            }
        }
    }
}

// -------------------- 4) persistent Sinkhorn rounds (vectorized) ------------
// one-pass online logsumexp; 256-element tiles via 2x LDG.128 per lane.
__device__ __forceinline__ void sink_row_v(const float* __restrict__ Crow, int n,
                                           const float* __restrict__ pot,
                                           float b2, float s1, float eps,
                                           const float* __restrict__ sPotAll,
                                           float* __restrict__ potOut,
                                           int outIdx, int finalMode, int lane) {
    const float4* __restrict__ C4 = reinterpret_cast<const float4*>(Crow);
    int npad4 = (n + 3) >> 2;
    float m = SENT, S = 0.f;
    for (int b4 = 0; b4 < npad4; b4 += 64) {
        int i0 = b4 + lane, i1 = b4 + 32 + lane;
        int i0c = min(i0, npad4 - 1), i1c = min(i1, npad4 - 1);
        float4 c0 = C4[i0c];
        float4 c1 = C4[i1c];
        int e0 = i0c * 4, e1 = i1c * 4;
        float t0 = fmaf(pot[e0 + 0] - c0.x, s1, b2);
        float t1 = fmaf(pot[e0 + 1] - c0.y, s1, b2);
        float t2 = fmaf(pot[e0 + 2] - c0.z, s1, b2);
        float t3 = fmaf(pot[e0 + 3] - c0.w, s1, b2);
        float t4 = fmaf(pot[e1 + 0] - c1.x, s1, b2);
        float t5 = fmaf(pot[e1 + 1] - c1.y, s1, b2);
        float t6 = fmaf(pot[e1 + 2] - c1.z, s1, b2);
        float t7 = fmaf(pot[e1 + 3] - c1.w, s1, b2);
        if (i0 >= npad4) { t0 = SENT; t1 = SENT; t2 = SENT; t3 = SENT; }
        if (i1 >= npad4) { t4 = SENT; t5 = SENT; t6 = SENT; t7 = SENT; }
        float mt = fmaxf(fmaxf(fmaxf(t0, t1), fmaxf(t2, t3)),
                         fmaxf(fmaxf(t4, t5), fmaxf(t6, t7)));
        float c2 = fmaxf(m, mt);
        float Sn = S * ex2_fast(m - c2);
        Sn += ex2_fast(t0 - c2); Sn += ex2_fast(t1 - c2);
        Sn += ex2_fast(t2 - c2); Sn += ex2_fast(t3 - c2);
        Sn += ex2_fast(t4 - c2); Sn += ex2_fast(t5 - c2);
        Sn += ex2_fast(t6 - c2); Sn += ex2_fast(t7 - c2);
        m = c2; S = Sn;
    }
#pragma unroll
    for (int o = 16; o; o >>= 1) {
        float mo = __shfl_xor_sync(0xffffffffu, m, o);
        float So = __shfl_xor_sync(0xffffffffu, S, o);
        float c2 = fmaxf(m, mo);
        S = S * ex2_fast(m - c2) + So * ex2_fast(mo - c2);
        m = c2;
    }
    if (lane == 0) {
        float lse = (m + log2f(S)) * LN2_F;
        float outv = -eps * lse;
        __stcg(&potOut[outIdx], finalMode ? outv : 0.5f * (sPotAll[outIdx] + outv));
    }
}

__global__ __launch_bounds__(1024, 1) void k_rounds(float* __restrict__ out) {
    __shared__ float sPot[POT_SZ + 4];          // snapshot + 4 safe pad entries
    __shared__ int   sRow[NSEG + 1], sCol[NSEG + 1];
    __shared__ int   sN[NSEG], sStr[NSEG], sPO[NSEG], sOut[NSEG];
    __shared__ float sB2[NSEG];
    __shared__ float* sCB[NSEG];
    __shared__ float seps[24], sinv[24];
    __shared__ int sns;
    __shared__ float sred[1024];
    int tid = threadIdx.x, lane = tid & 31;
    if (tid < NSEG + 1) { sRow[tid] = g_segRow[tid]; sCol[tid] = g_segCol[tid]; }
    if (tid >= 64 && tid < 64 + NSEG) {
        int s = tid - 64;
        sN[s] = g_segN[s]; sStr[s] = g_segStride[s]; sPO[s] = g_segPot[s];
        sOut[s] = g_segOut[s]; sB2[s] = g_segB2[s]; sCB[s] = g_segC[s];
    }
    if (tid == 0) {
        double e = 16.0; int c = 0;
        while (e > 0.0025) { seps[c] = (float)e; sinv[c] = (float)(1.0 / (double)(float)e); c++; e *= 0.64; }
        seps[c] = 0.0025f; sinv[c] = (float)(1.0 / (double)0.0025f); c++;
        sns = c;
    }
    __syncthreads();
    int ns = sns;
    int totalCols = sCol[NSEG];
    int nwarps = GRIDB * 32;
    int T = (totalCols + nwarps - 1) / nwarps;
    int w = blockIdx.x * 32 + (tid >> 5);
    int wT = w * T;
    int wEnd = wT + T;

    for (int s = 0; s <= ns; s++) {
        int fin = (s == ns);
        int ei = fin ? ns - 1 : s;
        float eps = seps[ei];
        float s1 = sinv[ei] * LOG2E_F;
        const float* potIn = g_pot[s & 1];
        float* potOut = g_pot[(s + 1) & 1];
        // vectorized L2-coherent snapshot
        {
            const float4* src = reinterpret_cast<const float4*>(potIn);
            float4* dst = reinterpret_cast<float4*>(sPot);
            for (int i = tid; i < POT_SZ / 4; i += 1024) dst[i] = __ldcg(src + i);
            if (tid < 4) sPot[POT_SZ + tid] = 0.f;
        }
        __syncthreads();
        if (wT < totalCols) {
            int sg = 0;
            while (sCol[sg + 1] <= wT) sg++;          // first seg whose end prefix > wT (has sN>0)
            int r = sRow[sg] + (wT - sCol[sg] + sN[sg] - 1) / sN[sg];
            while (r < NROWS) {
                while (r >= sRow[sg + 1]) sg++;
                int p = r - sRow[sg];
                int n = sN[sg];
                int pfx = sCol[sg] + p * n;
                if (pfx >= wEnd) break;
                if (n > 0)
                    sink_row_v(sCB[sg] + (size_t)p * sStr[sg], n, sPot + sPO[sg],
                               sB2[sg], s1, eps, sPot, potOut, sOut[sg] + p, fin, lane);
                r++;
            }
        }
        __syncthreads();
        if (tid == 0) {
            red_release_add1(&g_barCnt);
            unsigned target = (unsigned)(s + 1) * gridDim.x;
            while (ld_acquire_u32(&g_barCnt) < target) { }
        }
        __syncthreads();
    }
    if (blockIdx.x != 0) {
        if (tid == 0) red_release_add1(&g_exitCnt);
        return;
    }
    // block 0: final divergence reduction (L2-coherent reads)
    const float* pf = g_pot[(ns + 1) & 1];
    float acc = 0.f;
    for (int p = tid; p < NN; p += 1024) {
        int k = g_clx[p];
        if (g_valid[k]) acc += (__ldcg(&pf[FAB_OFF + p]) - __ldcg(&pf[FAA_OFF + p])) / (float)g_cntx[k];
    }
    for (int p = tid; p < MM; p += 1024) {
        int k = g_cly[p];
        if (g_valid[k]) acc += (__ldcg(&pf[GAB_OFF + p]) - __ldcg(&pf[GBB_OFF + p])) / (float)g_cnty[k];
    }
    sred[tid] = acc;
    __syncthreads();
    for (int st = 512; st; st >>= 1) {
        if (tid < st) sred[tid] += sred[tid + st];
        __syncthreads();
    }
    if (tid == 0) {
        out[0] = sred[0] + g_lossfil;
        while (ld_acquire_u32(&g_exitCnt) < (unsigned)(gridDim.x - 1)) { }
        *((volatile unsigned*)&g_barCnt) = 0;
        *((volatile unsigned*)&g_exitCnt) = 0;
    }
}

// -------------------- host launch -------------------------------------------
extern "C" void kernel_launch(void* const* d_in, const int* in_sizes, int n_in,
                              void* d_out, int out_size) {
    const float* x    = (const float*)d_in[0];
    const float* cc   = (const float*)d_in[1];
    const float* fill = (const float*)d_in[2];
    const float* y    = (const float*)d_in[3];
    const int*   pred = (const int*)d_in[4];
    float* out = (float*)d_out;

    k_prep<<<(NN + MM + 255) / 256, 256>>>(x, cc, y);
    k_lists<<<1, 256>>>(pred, fill);
    k_cost<<<COST_GRID, 256>>>(x, y);
    k_rounds<<<GRIDB, 1024>>>(out);
}

// round 15
// speedup vs baseline: 1.9200x; 1.9200x over previous
#include <cuda_runtime.h>
#include <math.h>

#define NN 2048
#define MM 2048
#define KC 8
#define DD 64

#define FAB_OFF 0
#define GAB_OFF NN
#define FAA_OFF (NN + MM)
#define GBB_OFF (2 * NN + MM)
#define POT_SZ  (2 * (NN + MM))
#define NROWS   (2 * (NN + MM))
#define NSEG    (4 * KC)

#define LOG2E_F 1.4426950408889634f
#define LN2_F   0.6931471805599453f
#define SENT    -3.4e38f

#define GRIDB 148
#define COST_GRID 5120
#define C_MAX 19000000      // worst case 16.8M + 256-pad margin

// -------------------- static device scratch ---------------------------------
__device__ int   g_predx[NN];
__device__ int   g_ix[NN], g_iy[MM];
__device__ int   g_clx[NN], g_cly[MM];
__device__ int   g_cntx[KC], g_cnty[KC];
__device__ int   g_offx[KC + 1], g_offy[KC + 1];
__device__ int   g_offXY[KC], g_offYX[KC], g_offXX[KC], g_offYY[KC]; // unified C offsets
__device__ float g_l2cx[KC], g_l2cy[KC];
__device__ int   g_valid[KC];
__device__ float g_lossfil;
__device__ int   g_tOff[NSEG + 1];
__device__ unsigned g_barCnt;
__device__ unsigned g_exitCnt;
__device__ float g_hx[NN], g_hy[MM];
__device__ float g_b2pot[POT_SZ];       // -log2(count) of each pot index's side
// per-cluster segment tables (built once)
__device__ int   g_segRow[NSEG + 1];
__device__ int   g_segCb[NSEG];         // C base offset (unified)
__device__ int   g_segStride[NSEG];     // padded stride (multiple of 256)
__device__ int   g_segPot[NSEG];
__device__ int   g_segOut[NSEG];
// packed per-row descriptors: x=C ofs, y=pot ofs, z=stride, w=outIdx
__device__ int4  g_rowDesc[NROWS];
// unified padded cost buffer
__device__ float g_C[C_MAX];
__device__ float g_pot[2][POT_SZ];

__device__ __forceinline__ float ex2_fast(float x) {
    float r;
    asm("ex2.approx.ftz.f32 %0, %1;" : "=f"(r) : "f"(x));
    return r;
}
__device__ __forceinline__ void red_release_add1(unsigned* p) {
    asm volatile("red.release.gpu.add.u32 [%0], 1;" :: "l"(p) : "memory");
}
__device__ __forceinline__ unsigned ld_acquire_u32(unsigned* p) {
    unsigned v;
    asm volatile("ld.acquire.gpu.u32 %0, [%1];" : "=r"(v) : "l"(p) : "memory");
    return v;
}

// -------------------- 1) fused assign + norms -------------------------------
__global__ void k_prep(const float* __restrict__ x, const float* __restrict__ cc,
                       const float* __restrict__ y) {
    __shared__ float scc[KC * DD];
    for (int idx = threadIdx.x; idx < KC * DD; idx += blockDim.x) scc[idx] = cc[idx];
    __syncthreads();
    int t = blockIdx.x * blockDim.x + threadIdx.x;
    if (t < NN) {
        float xr[DD];
        float nrm = 0.f;
        const float4* xv = reinterpret_cast<const float4*>(x + (size_t)t * DD);
#pragma unroll
        for (int q = 0; q < DD / 4; q++) {
            float4 v = xv[q];
            xr[q*4+0]=v.x; xr[q*4+1]=v.y; xr[q*4+2]=v.z; xr[q*4+3]=v.w;
            nrm += v.x*v.x + v.y*v.y + v.z*v.z + v.w*v.w;
        }
        g_hx[t] = 0.5f * nrm;
        float best = 3.4e38f; int bk = 0;
#pragma unroll
        for (int k = 0; k < KC; k++) {
            float s = 0.f;
#pragma unroll 16
            for (int d = 0; d < DD; d++) {
                float u = xr[d] - scc[k * DD + d];
                s = fmaf(u, u, s);
            }
            if (s < best) { best = s; bk = k; }
        }
        g_predx[t] = bk;
    } else if (t < NN + MM) {
        int j = t - NN;
        const float4* v = reinterpret_cast<const float4*>(y + (size_t)j * DD);
        float s = 0.f;
#pragma unroll
        for (int q = 0; q < DD / 4; q++) { float4 a = v[q]; s += a.x*a.x + a.y*a.y + a.z*a.z + a.w*a.w; }
        g_hy[j] = 0.5f * s;
    }
}

// -------------------- 2) lists + offsets + descriptors ----------------------
__global__ void k_lists(const int* __restrict__ predy32, const float* __restrict__ fill) {
    __shared__ int sBase[2][KC];
    __shared__ int sCnt[2][KC];
    __shared__ int sOr;
    int w = threadIdx.x >> 5, lane = threadIdx.x & 31;

    if (threadIdx.x == 0) sOr = 0;
    __syncthreads();
    int orv = 0;
    for (int i = threadIdx.x; i < MM / 2; i += blockDim.x) orv |= predy32[2 * i + 1];
    atomicOr(&sOr, orv);
    __syncthreads();
    const int stride = (sOr == 0) ? 2 : 1;   // int64 (odd words 0) vs int32

    if (w < 2) {
        int nElem = (w == 0) ? NN : MM;
        int cnt[KC];
#pragma unroll
        for (int k = 0; k < KC; k++) cnt[k] = 0;
        for (int ch = 0; ch < nElem / 32; ch++) {
            int i = ch * 32 + lane;
            int v = (w == 0) ? g_predx[i] : (predy32[i * stride] & 7);
#pragma unroll
            for (int k = 0; k < KC; k++) cnt[k] += (v == k);
        }
#pragma unroll
        for (int k = 0; k < KC; k++) {
            int s = cnt[k];
            for (int o = 16; o; o >>= 1) s += __shfl_down_sync(0xffffffffu, s, o);
            if (lane == 0) sCnt[w][k] = s;
        }
        __syncwarp();
        if (lane == 0) {
            int off = 0;
            for (int k = 0; k < KC; k++) {
                int c = sCnt[w][k];
                sBase[w][k] = off;
                if (w == 0) { g_cntx[k] = c; g_offx[k] = off; }
                else        { g_cnty[k] = c; g_offy[k] = off; }
                off += c;
            }
            if (w == 0) g_offx[KC] = off; else g_offy[KC] = off;
        }
        __syncwarp();
        for (int ch = 0; ch < nElem / 32; ch++) {
            int i = ch * 32 + lane;
            int v = (w == 0) ? g_predx[i] : (predy32[i * stride] & 7);
            unsigned mask = __match_any_sync(0xffffffffu, v);
            unsigned lt = (1u << lane) - 1u;
            int rank = __popc(mask & lt);
            int myBase = sBase[w][v];
            __syncwarp();
            int pos = myBase + rank;
            if (w == 0) { g_ix[pos] = i; g_clx[pos] = v; }
            else        { g_iy[pos] = i; g_cly[pos] = v; }
            if ((mask & lt) == 0) sBase[w][v] = myBase + __popc(mask);
            __syncwarp();
        }
    }
    __syncthreads();
    if (threadIdx.x == 0) {
        float lf = 0.f;
        int oC = 0, rowAcc = 0;
        for (int k = 0; k < KC; k++) {
            int cx = g_cntx[k], cy = g_cnty[k];
            int cxp = (cx + 255) & ~255, cyp = (cy + 255) & ~255;
            float d = (float)cx / (float)NN - fill[k];
            lf += d * d;
            float l2x = log2f((float)(cx > 0 ? cx : 1));
            float l2y = log2f((float)(cy > 0 ? cy : 1));
            g_l2cx[k] = l2x; g_l2cy[k] = l2y;
            g_valid[k] = (cx > 0 && cy > 0) ? 1 : 0;
            int s = 4 * k;
            // fab: rows cx, reduce cy
            g_segRow[s] = rowAcc; g_segCb[s] = oC; g_segStride[s] = cyp;
            g_segPot[s] = GAB_OFF + g_offy[k]; g_segOut[s] = FAB_OFF + g_offx[k];
            g_offXY[k] = oC; rowAcc += cx; oC += cx * cyp; s++;
            // gab: rows cy, reduce cx
            g_segRow[s] = rowAcc; g_segCb[s] = oC; g_segStride[s] = cxp;
            g_segPot[s] = FAB_OFF + g_offx[k]; g_segOut[s] = GAB_OFF + g_offy[k];
            g_offYX[k] = oC; rowAcc += cy; oC += cy * cxp; s++;
            // faa: rows cx, reduce cx
            g_segRow[s] = rowAcc; g_segCb[s] = oC; g_segStride[s] = cxp;
            g_segPot[s] = FAA_OFF + g_offx[k]; g_segOut[s] = FAA_OFF + g_offx[k];
            g_offXX[k] = oC; rowAcc += cx; oC += cx * cxp; s++;
            // gbb: rows cy, reduce cy
            g_segRow[s] = rowAcc; g_segCb[s] = oC; g_segStride[s] = cyp;
            g_segPot[s] = GBB_OFF + g_offy[k]; g_segOut[s] = GBB_OFF + g_offy[k];
            g_offYY[k] = oC; rowAcc += cy; oC += cy * cyp;
        }
        g_segRow[NSEG] = rowAcc;
        g_lossfil = lf / (float)KC;
        g_tOff[0] = 0;
        for (int f = 0; f < 4; f++)
            for (int k = 0; k < KC; k++) {
                int cx = g_cntx[k], cy = g_cnty[k];
                int nr = (f == 0 || f == 2) ? cx : cy;
                int nc = (f == 1 || f == 2) ? cx : cy;
                int ncp = (nc + 255) & ~255;
                int idx = f * KC + k;
                g_tOff[idx + 1] = g_tOff[idx] + ((nr + 63) / 64) * (ncp / 64);
            }
    }
    __syncthreads();
    // b2pot table: -log2(count) of the side each pot index belongs to
    for (int i = threadIdx.x; i < NN; i += blockDim.x) {
        float b = -g_l2cx[g_clx[i]];
        g_b2pot[FAB_OFF + i] = b; g_b2pot[FAA_OFF + i] = b;
    }
    for (int j = threadIdx.x; j < MM; j += blockDim.x) {
        float b = -g_l2cy[g_cly[j]];
        g_b2pot[GAB_OFF + j] = b; g_b2pot[GBB_OFF + j] = b;
    }
    // packed row descriptors
    for (int row = threadIdx.x; row < NROWS; row += blockDim.x) {
        int sg = 0;
        while (row >= g_segRow[sg + 1]) sg++;
        int p = row - g_segRow[sg];
        int4 d;
        d.x = g_segCb[sg] + p * g_segStride[sg];
        d.y = g_segPot[sg];
        d.z = g_segStride[sg];
        d.w = g_segOut[sg] + p;
        g_rowDesc[row] = d;
    }
    for (int i = threadIdx.x; i < POT_SZ; i += blockDim.x) g_pot[0][i] = 0.f;
}

// -------------------- 3) cost submatrices (unified, 256-padded, INF fill) ---
__global__ __launch_bounds__(256) void k_cost(const float* __restrict__ x,
                                              const float* __restrict__ y) {
    __shared__ float sR[64][65];
    __shared__ float sCt[64][68];
    __shared__ float sHr[64], sHc[64];
    __shared__ int sOff[NSEG + 1];
    int tid = threadIdx.x;
    if (tid < NSEG + 1) sOff[tid] = g_tOff[tid];
    __syncthreads();
    int bt = blockIdx.x;
    if (bt >= sOff[NSEG]) return;
    int e = 0;
    while (bt >= sOff[e + 1]) e++;
    int f = e >> 3, k = e & 7;
    int ti = bt - sOff[e];
    int cx = g_cntx[k], cy = g_cnty[k], ox = g_offx[k], oy = g_offy[k];
    int nr, nc, obase;
    const int *rl, *cl; const float *rp, *cp, *rh, *chv;
    if (f == 0)      { nr = cx; nc = cy; rl = g_ix + ox; cl = g_iy + oy; rp = x; cp = y; rh = g_hx; chv = g_hy; obase = g_offXY[k]; }
    else if (f == 1) { nr = cy; nc = cx; rl = g_iy + oy; cl = g_ix + ox; rp = y; cp = x; rh = g_hy; chv = g_hx; obase = g_offYX[k]; }
    else if (f == 2) { nr = cx; nc = cx; rl = g_ix + ox; cl = g_ix + ox; rp = x; cp = x; rh = g_hx; chv = g_hx; obase = g_offXX[k]; }
    else             { nr = cy; nc = cy; rl = g_iy + oy; cl = g_iy + oy; rp = y; cp = y; rh = g_hy; chv = g_hy; obase = g_offYY[k]; }
    if (nr == 0 || nc == 0) return;
    int ncp = (nc + 255) & ~255;
    int nct = ncp >> 6;
    int r0 = (ti / nct) * 64;
    int c0 = (ti % nct) * 64;
    const float F_INF = __int_as_float(0x7f800000);

    for (int idx = tid; idx < 64 * DD; idx += 256) {
        int r = idx >> 6, d = idx & 63;
        int gi = rl[min(r0 + r, nr - 1)];
        sR[r][d] = rp[(size_t)gi * DD + d];
    }
    for (int idx = tid; idx < 64 * DD; idx += 256) {
        int c = idx >> 6, d = idx & 63;
        int gi = cl[min(c0 + c, nc - 1)];
        sCt[d][c] = cp[(size_t)gi * DD + d];
    }
    if (tid < 64)       sHr[tid]      = rh[rl[min(r0 + tid, nr - 1)]];
    else if (tid < 128) sHc[tid - 64] = chv[cl[min(c0 + tid - 64, nc - 1)]];
    __syncthreads();

    int rg = tid >> 4, cg = tid & 15;
    float acc[4][4];
#pragma unroll
    for (int i = 0; i < 4; i++)
#pragma unroll
        for (int j = 0; j < 4; j++) acc[i][j] = 0.f;

#pragma unroll 8
    for (int d = 0; d < DD; d++) {
        float4 cv = *reinterpret_cast<const float4*>(&sCt[d][cg * 4]);
        float r0v = sR[rg * 4 + 0][d];
        float r1v = sR[rg * 4 + 1][d];
        float r2v = sR[rg * 4 + 2][d];
        float r3v = sR[rg * 4 + 3][d];
        acc[0][0]=fmaf(r0v,cv.x,acc[0][0]); acc[0][1]=fmaf(r0v,cv.y,acc[0][1]);
        acc[0][2]=fmaf(r0v,cv.z,acc[0][2]); acc[0][3]=fmaf(r0v,cv.w,acc[0][3]);
        acc[1][0]=fmaf(r1v,cv.x,acc[1][0]); acc[1][1]=fmaf(r1v,cv.y,acc[1][1]);
        acc[1][2]=fmaf(r1v,cv.z,acc[1][2]); acc[1][3]=fmaf(r1v,cv.w,acc[1][3]);
        acc[2][0]=fmaf(r2v,cv.x,acc[2][0]); acc[2][1]=fmaf(r2v,cv.y,acc[2][1]);
        acc[2][2]=fmaf(r2v,cv.z,acc[2][2]); acc[2][3]=fmaf(r2v,cv.w,acc[2][3]);
        acc[3][0]=fmaf(r3v,cv.x,acc[3][0]); acc[3][1]=fmaf(r3v,cv.y,acc[3][1]);
        acc[3][2]=fmaf(r3v,cv.z,acc[3][2]); acc[3][3]=fmaf(r3v,cv.w,acc[3][3]);
    }

#pragma unroll
    for (int i = 0; i < 4; i++) {
        int rr = r0 + rg * 4 + i;
        if (rr < nr) {
            float hr = sHr[rg * 4 + i];
            size_t rowb = (size_t)obase + (size_t)rr * ncp;
#pragma unroll
            for (int j = 0; j < 4; j++) {
                int cc = c0 + cg * 4 + j;
                if (cc < nc)       g_C[rowb + cc] = fmaxf(hr + sHc[cg * 4 + j] - acc[i][j], 0.f);
                else if (cc < ncp) g_C[rowb + cc] = F_INF;   // padding: exp contributes 0
            }
        }
    }
}

// -------------------- 4) persistent Sinkhorn rounds -------------------------
// inner loop: t = fmaf(C, -s1, pot')   (pot' = pot*s1 + b2, INF padding = free mask)
__device__ __forceinline__ void sink_row(int4 d, const float* __restrict__ sPot,
                                         float ns1, float c3,
                                         const float* __restrict__ potInRaw,
                                         float* __restrict__ potOut,
                                         int fin, int lane) {
    if (d.z == 0) { if (lane == 0) __stcg(&potOut[d.w], 0.f); return; }
    const float* __restrict__ C = g_C + d.x;
    const float* __restrict__ P = sPot + d.y;
    float rawPrev = 0.f;
    if (!fin) rawPrev = __ldcg(potInRaw + d.w);
    float m = SENT, S = 0.f;
    int ntiles = d.z >> 8;
    for (int t = 0; t < ntiles; t++) {
        int base = t * 256 + lane;
        float tv[8];
#pragma unroll
        for (int q = 0; q < 8; q++)
            tv[q] = fmaf(C[base + q * 32], ns1, P[base + q * 32]);
        float mt = fmaxf(fmaxf(fmaxf(tv[0], tv[1]), fmaxf(tv[2], tv[3])),
                         fmaxf(fmaxf(tv[4], tv[5]), fmaxf(tv[6], tv[7])));
        float c2 = fmaxf(m, mt);
        float Sn = S * ex2_fast(m - c2);
#pragma unroll
        for (int q = 0; q < 8; q++) Sn += ex2_fast(tv[q] - c2);
        m = c2; S = Sn;
    }
    // two-phase warp merge: max-reduce, rescale once, sum-reduce
    float mloc = m;
#pragma unroll
    for (int o = 16; o; o >>= 1) m = fmaxf(m, __shfl_xor_sync(0xffffffffu, m, o));
    float Sp = S * ex2_fast(mloc - m);
#pragma unroll
    for (int o = 16; o; o >>= 1) Sp += __shfl_xor_sync(0xffffffffu, Sp, o);
    if (lane == 0) {
        float outv = c3 * (m + log2f(Sp));
        __stcg(&potOut[d.w], fin ? outv : 0.5f * (rawPrev + outv));
    }
}

__global__ __launch_bounds__(1024, 1) void k_rounds(float* __restrict__ out) {
    __shared__ float sPot[POT_SZ + 256];        // scaled snapshot + stride pad
    __shared__ float seps[24], sinv[24];
    __shared__ int sns;
    __shared__ float sred[1024];
    int tid = threadIdx.x, lane = tid & 31;
    int nwarps = GRIDB * 32;
    int gwarp = blockIdx.x * 32 + (tid >> 5);
    if (tid == 0) {
        double e = 16.0; int c = 0;
        while (e > 0.0025) { seps[c] = (float)e; sinv[c] = (float)(1.0 / (double)(float)e); c++; e *= 0.64; }
        seps[c] = 0.0025f; sinv[c] = (float)(1.0 / (double)0.0025f); c++;
        sns = c;
    }
    // preload this warp's (at most 2) row descriptors into registers
    int r1 = gwarp + nwarps;
    int4 d0 = g_rowDesc[gwarp];
    int4 d1 = (r1 < NROWS) ? g_rowDesc[r1] : make_int4(0, 0, 0, -1);
    int h1 = (r1 < NROWS);
    // zero the pad tail once
    if (tid < 64) {
        float4 z = make_float4(0.f, 0.f, 0.f, 0.f);
        reinterpret_cast<float4*>(sPot + POT_SZ)[tid] = z;
    }
    __syncthreads();
    int ns = sns;
    for (int s = 0; s <= ns; s++) {
        int fin = (s == ns);
        int ei = fin ? ns - 1 : s;
        float eps = seps[ei];
        float s1 = sinv[ei] * LOG2E_F;
        float ns1 = -s1;
        float c3 = -eps * LN2_F;
        const float* potIn = g_pot[s & 1];
        float* potOut = g_pot[(s + 1) & 1];
        // scaled snapshot: sPot = pot*s1 + b2  (L2-coherent reads of pot)
        {
            const float4* src = reinterpret_cast<const float4*>(potIn);
            const float4* b2v = reinterpret_cast<const float4*>(g_b2pot);
            float4* dst = reinterpret_cast<float4*>(sPot);
            for (int i = tid; i < POT_SZ / 4; i += 1024) {
                float4 a = __ldcg(src + i);
                float4 b = b2v[i];
                float4 r;
                r.x = fmaf(a.x, s1, b.x); r.y = fmaf(a.y, s1, b.y);
                r.z = fmaf(a.z, s1, b.z); r.w = fmaf(a.w, s1, b.w);
                dst[i] = r;
            }
        }
        __syncthreads();
        sink_row(d0, sPot, ns1, c3, potIn, potOut, fin, lane);
        if (h1) sink_row(d1, sPot, ns1, c3, potIn, potOut, fin, lane);
        __syncthreads();
        if (tid == 0) {
            red_release_add1(&g_barCnt);
            unsigned target = (unsigned)(s + 1) * gridDim.x;
            while (ld_acquire_u32(&g_barCnt) < target) { }
        }
        __syncthreads();
    }
    if (blockIdx.x != 0) {
        if (tid == 0) red_release_add1(&g_exitCnt);
        return;
    }
    // block 0: final divergence reduction (L2-coherent reads)
    const float* pf = g_pot[(ns + 1) & 1];
    float acc = 0.f;
    for (int p = tid; p < NN; p += 1024) {
        int k = g_clx[p];
        if (g_valid[k]) acc += (__ldcg(&pf[FAB_OFF + p]) - __ldcg(&pf[FAA_OFF + p])) / (float)g_cntx[k];
    }
    for (int p = tid; p < MM; p += 1024) {
        int k = g_cly[p];
        if (g_valid[k]) acc += (__ldcg(&pf[GAB_OFF + p]) - __ldcg(&pf[GBB_OFF + p])) / (float)g_cnty[k];
    }
    sred[tid] = acc;
    __syncthreads();
    for (int st = 512; st; st >>= 1) {
        if (tid < st) sred[tid] += sred[tid + st];
        __syncthreads();
    }
    if (tid == 0) {
        out[0] = sred[0] + g_lossfil;
        while (ld_acquire_u32(&g_exitCnt) < (unsigned)(gridDim.x - 1)) { }
        *((volatile unsigned*)&g_barCnt) = 0;
        *((volatile unsigned*)&g_exitCnt) = 0;
    }
}

// -------------------- host launch -------------------------------------------
extern "C" void kernel_launch(void* const* d_in, const int* in_sizes, int n_in,
                              void* d_out, int out_size) {
    const float* x    = (const float*)d_in[0];
    const float* cc   = (const float*)d_in[1];
    const float* fill = (const float*)d_in[2];
    const float* y    = (const float*)d_in[3];
    const int*   pred = (const int*)d_in[4];
    float* out = (float*)d_out;

    k_prep<<<(NN + MM + 255) / 256, 256>>>(x, cc, y);
    k_lists<<<1, 256>>>(pred, fill);
    k_cost<<<COST_GRID, 256>>>(x, y);
    k_rounds<<<GRIDB, 1024>>>(out);
}